// round 13
// baseline (speedup 1.0000x reference)
#include <cuda_runtime.h>
#include <cuda_bf16.h>
#include <cstdint>

typedef uint32_t u32;
typedef uint16_t u16;

#define NB 8
#define NC 256
#define NN 1024
#define NT 3

// bf16 scratch: Q^T/K^T [.., n, c], V [.., c, n]
__device__ __align__(16) u16 g_QpT[NB * NN * NC];
__device__ __align__(16) u16 g_KpT[NT * NB * NN * NC];
__device__ __align__(16) u16 g_Vp [NT * NB * NC * NN];
// P = exp(S/16) bf16 [t*8+b][q][k], row sums
__device__ __align__(16) u16   g_P[(size_t)NT * NB * NN * NN];
__device__ float g_lacc[NT * NB * NN];

// ---------------- helpers ----------------
__device__ __forceinline__ u32 smem_u32(const void* p) {
    u32 a;
    asm("{ .reg .u64 t; cvta.to.shared.u64 t, %1; cvt.u32.u64 %0, t; }"
        : "=r"(a) : "l"(p));
    return a;
}
__device__ __forceinline__ void cp16(u32 dst, const void* src) {
    asm volatile("cp.async.cg.shared.global [%0], [%1], 16;"
                 :: "r"(dst), "l"(src) : "memory");
}
__device__ __forceinline__ void cp_commit() {
    asm volatile("cp.async.commit_group;" ::: "memory");
}

__device__ __forceinline__ u32 to_tf32(float f) {
    u32 r; asm("cvt.rna.tf32.f32 %0, %1;" : "=r"(r) : "f"(f)); return r;
}
__device__ __forceinline__ float rnd_tf32(float f) { return __uint_as_float(to_tf32(f)); }

__device__ __forceinline__ u32 pack_bf16(float lo, float hi) {
    u32 r; asm("cvt.rn.bf16x2.f32 %0, %1, %2;" : "=r"(r) : "f"(hi), "f"(lo)); return r;
}
__device__ __forceinline__ u16 bf16_bits(float f) {
    u16 r; asm("cvt.rn.bf16.f32 %0, %1;" : "=h"(r) : "f"(f)); return r;
}

__device__ __forceinline__ void mma_tf32(float* d, const u32* a, const u32* b) {
    asm volatile(
        "mma.sync.aligned.m16n8k8.row.col.f32.tf32.tf32.f32 "
        "{%0,%1,%2,%3}, {%4,%5,%6,%7}, {%8,%9}, {%0,%1,%2,%3};"
        : "+f"(d[0]), "+f"(d[1]), "+f"(d[2]), "+f"(d[3])
        : "r"(a[0]), "r"(a[1]), "r"(a[2]), "r"(a[3]), "r"(b[0]), "r"(b[1]));
}
__device__ __forceinline__ void mma_bf16(float* d, const u32* a, const u32* b) {
    asm volatile(
        "mma.sync.aligned.m16n8k16.row.col.f32.bf16.bf16.f32 "
        "{%0,%1,%2,%3}, {%4,%5,%6,%7}, {%8,%9}, {%0,%1,%2,%3};"
        : "+f"(d[0]), "+f"(d[1]), "+f"(d[2]), "+f"(d[3])
        : "r"(a[0]), "r"(a[1]), "r"(a[2]), "r"(a[3]), "r"(b[0]), "r"(b[1]));
}

__device__ __forceinline__ float fast_exp(float x) {
    float t = fmaf(x, 1.4426950408889634f, 12582912.0f);
    float n = t - 12582912.0f;
    int   e = __float_as_int(t) << 23;
    float r = fmaf(x, 1.4426950408889634f, -n);
    float p = 1.3333558146e-3f;
    p = fmaf(p, r, 9.6181291076e-3f);
    p = fmaf(p, r, 5.5504108665e-2f);
    p = fmaf(p, r, 2.4022650696e-1f);
    p = fmaf(p, r, 6.9314718056e-1f);
    p = fmaf(p, r, 1.0f);
    return __int_as_float(__float_as_int(p) + e);
}

__global__ void zero_lacc_kernel() {
    g_lacc[blockIdx.x * 1024 + threadIdx.x] = 0.0f;
}

// ---------------------------------------------------------------------------
// Projection via tf32 mma (unchanged, proven): Out[o][n] = W @ X + b
// ---------------------------------------------------------------------------
#define PW_STR 36
#define PX_STR 264
#define PSM_BYTES (64 * PW_STR * 4 + 32 * PX_STR * 4)

__global__ __launch_bounds__(256) void proj_kernel(
    const float* __restrict__ Wq, const float* __restrict__ bq,
    const float* __restrict__ Wk, const float* __restrict__ bk,
    const float* __restrict__ Wv, const float* __restrict__ bv,
    const float* __restrict__ xs, const float* __restrict__ x0,
    const float* __restrict__ x1, const float* __restrict__ x2)
{
    __shared__ __align__(16) char psm[PSM_BYTES];
    float* Wsf = (float*)psm;
    float* Xsf = (float*)(psm + 64 * PW_STR * 4);
    u16*   stg = (u16*)psm;

    const int tid  = threadIdx.x;
    const int wid  = tid >> 5, lane = tid & 31;
    const int gr   = lane >> 2, j = lane & 3;
    const int ow   = wid & 1, nw = wid >> 1;
    const int n0   = blockIdx.x * 256;
    const int o0   = blockIdx.y * 64;
    const int z    = blockIdx.z;
    const int p    = z >> 3, b = z & 7;

    const float* W; const float* bias; const float* X;
    u16* dst; bool vmode;
    if (p == 0) {
        W = Wq; bias = bq; X = xs + (size_t)b * NC * NN;
        dst = g_QpT + (size_t)b * NN * NC; vmode = false;
    } else if (p <= 3) {
        W = Wk; bias = bk;
        const float* tf = (p == 1) ? x0 : ((p == 2) ? x1 : x2);
        X = tf + (size_t)b * NC * NN;
        dst = g_KpT + ((size_t)(p - 1) * NB + b) * NN * NC; vmode = false;
    } else {
        W = Wv; bias = bv;
        const float* tf = (p == 4) ? x0 : ((p == 5) ? x1 : x2);
        X = tf + (size_t)b * NC * NN;
        dst = g_Vp + ((size_t)(p - 4) * NB + b) * NC * NN; vmode = true;
    }

    float d[2][8][4];
#pragma unroll
    for (int mi = 0; mi < 2; mi++)
#pragma unroll
        for (int f = 0; f < 8; f++)
#pragma unroll
            for (int e = 0; e < 4; e++) d[mi][f][e] = 0.0f;

    for (int c0 = 0; c0 < NC; c0 += 32) {
        __syncthreads();
#pragma unroll
        for (int it = 0; it < 2; it++) {
            int idx = tid + 256 * it;
            int r = idx >> 3, c4 = (idx & 7) * 4;
            float4 w4 = *(const float4*)&W[(size_t)(o0 + r) * NC + c0 + c4];
            Wsf[r * PW_STR + c4 + 0] = rnd_tf32(w4.x);
            Wsf[r * PW_STR + c4 + 1] = rnd_tf32(w4.y);
            Wsf[r * PW_STR + c4 + 2] = rnd_tf32(w4.z);
            Wsf[r * PW_STR + c4 + 3] = rnd_tf32(w4.w);
        }
#pragma unroll
        for (int it = 0; it < 8; it++) {
            int idx = tid + 256 * it;
            int r = idx >> 6, n4 = (idx & 63) * 4;
            float4 x4 = *(const float4*)&X[(size_t)(c0 + r) * NN + n0 + n4];
            Xsf[r * PX_STR + n4 + 0] = rnd_tf32(x4.x);
            Xsf[r * PX_STR + n4 + 1] = rnd_tf32(x4.y);
            Xsf[r * PX_STR + n4 + 2] = rnd_tf32(x4.z);
            Xsf[r * PX_STR + n4 + 3] = rnd_tf32(x4.w);
        }
        __syncthreads();

#pragma unroll
        for (int kx = 0; kx < 4; kx++) {
            int k0 = kx * 8;
            u32 a[2][4];
#pragma unroll
            for (int mi = 0; mi < 2; mi++) {
                int row = ow * 32 + mi * 16 + gr;
                a[mi][0] = __float_as_uint(Wsf[row * PW_STR + k0 + j]);
                a[mi][1] = __float_as_uint(Wsf[(row + 8) * PW_STR + k0 + j]);
                a[mi][2] = __float_as_uint(Wsf[row * PW_STR + k0 + j + 4]);
                a[mi][3] = __float_as_uint(Wsf[(row + 8) * PW_STR + k0 + j + 4]);
            }
#pragma unroll
            for (int f = 0; f < 8; f++) {
                int n = nw * 64 + f * 8 + gr;
                u32 bb[2];
                bb[0] = __float_as_uint(Xsf[(k0 + j) * PX_STR + n]);
                bb[1] = __float_as_uint(Xsf[(k0 + j + 4) * PX_STR + n]);
                mma_tf32(d[0][f], a[0], bb);
                mma_tf32(d[1][f], a[1], bb);
            }
        }
    }

    float bi[2][2];
#pragma unroll
    for (int mi = 0; mi < 2; mi++) {
        bi[mi][0] = bias[o0 + ow * 32 + mi * 16 + gr];
        bi[mi][1] = bias[o0 + ow * 32 + mi * 16 + gr + 8];
    }

    if (vmode) {
#pragma unroll
        for (int mi = 0; mi < 2; mi++) {
            int row0 = o0 + ow * 32 + mi * 16 + gr;
#pragma unroll
            for (int f = 0; f < 8; f++) {
                int n = n0 + nw * 64 + f * 8 + 2 * j;
                *(u32*)&dst[(size_t)row0 * NN + n] =
                    pack_bf16(d[mi][f][0] + bi[mi][0], d[mi][f][1] + bi[mi][0]);
                *(u32*)&dst[(size_t)(row0 + 8) * NN + n] =
                    pack_bf16(d[mi][f][2] + bi[mi][1], d[mi][f][3] + bi[mi][1]);
            }
        }
    } else {
        __syncthreads();
#pragma unroll
        for (int mi = 0; mi < 2; mi++) {
            int row0 = ow * 32 + mi * 16 + gr;
#pragma unroll
            for (int f = 0; f < 8; f++) {
                int n = nw * 64 + f * 8 + 2 * j;
                stg[n * 72 + row0]           = bf16_bits(d[mi][f][0] + bi[mi][0]);
                stg[(n + 1) * 72 + row0]     = bf16_bits(d[mi][f][1] + bi[mi][0]);
                stg[n * 72 + row0 + 8]       = bf16_bits(d[mi][f][2] + bi[mi][1]);
                stg[(n + 1) * 72 + row0 + 8] = bf16_bits(d[mi][f][3] + bi[mi][1]);
            }
        }
        __syncthreads();
#pragma unroll
        for (int it = 0; it < 8; it++) {
            int idx = tid + 256 * it;
            int n = idx >> 3, u = (idx & 7) * 8;
            *(uint4*)&dst[(size_t)(n0 + n) * NC + o0 + u] = *(const uint4*)&stg[n * 72 + u];
        }
    }
}

// ---------------------------------------------------------------------------
// S-kernel: P = exp((Q K^T)/16), c-reduction in TWO cp.async-pipelined
// halves of 128 c. Grid (4 ktile(256), 8 qtile(128), 24 tb), 512 threads.
// ---------------------------------------------------------------------------
#define S2_K     34816                     // Q part size (128*272)
#define S2_STAGE 104448                    // Q + K per stage
#define S2_SMEM  208896

__global__ __launch_bounds__(512, 1) void s_kernel()
{
    extern __shared__ __align__(16) char smc[];
    const u32 smb = smem_u32(smc);

    const int tid  = threadIdx.x;
    const int wid  = tid >> 5, lane = tid & 31;
    const int gr   = lane >> 2, j = lane & 3;
    const int qg   = wid & 3, kg = wid >> 2;
    const int k0   = blockIdx.x * 256;
    const int q0   = blockIdx.y * 128;
    const int tb   = blockIdx.z;
    const int b    = tb & 7;

    const u16* Qg = g_QpT + ((size_t)b * NN + q0) * NC;
    const u16* Kg = g_KpT + ((size_t)tb * NN + k0) * NC;

    auto issueS = [&](int h) {
        u32 base = smb + (u32)h * S2_STAGE;
#pragma unroll
        for (int it = 0; it < 4; it++) {
            int idx = tid + 512 * it;
            int r = idx >> 4, u = (idx & 15) * 8;
            cp16(base + r * 272 + u * 2, &Qg[(size_t)r * NC + h * 128 + u]);
        }
#pragma unroll
        for (int it = 0; it < 8; it++) {
            int idx = tid + 512 * it;
            int r = idx >> 4, u = (idx & 15) * 8;
            cp16(base + S2_K + r * 272 + u * 2, &Kg[(size_t)r * NC + h * 128 + u]);
        }
        cp_commit();
    };

    issueS(0);
    issueS(1);

    float sacc[2][8][4];
#pragma unroll
    for (int mi = 0; mi < 2; mi++)
#pragma unroll
        for (int f = 0; f < 8; f++)
#pragma unroll
            for (int e = 0; e < 4; e++) sacc[mi][f][e] = 0.0f;

#pragma unroll
    for (int h = 0; h < 2; h++) {
        if (h == 0) { asm volatile("cp.async.wait_group 1;" ::: "memory"); }
        else        { asm volatile("cp.async.wait_group 0;" ::: "memory"); }
        __syncthreads();

        const char* Qs = smc + h * S2_STAGE;
        const char* Ks = Qs + S2_K;

#pragma unroll 4
        for (int cc = 0; cc < 128; cc += 16) {
            u32 a[2][4];
#pragma unroll
            for (int mi = 0; mi < 2; mi++) {
                const char* base = Qs + (qg * 32 + mi * 16 + gr) * 272 + (cc + 2 * j) * 2;
                a[mi][0] = *(const u32*)(base);
                a[mi][1] = *(const u32*)(base + 8 * 272);
                a[mi][2] = *(const u32*)(base + 16);
                a[mi][3] = *(const u32*)(base + 8 * 272 + 16);
            }
#pragma unroll
            for (int f = 0; f < 8; f++) {
                const char* kb = Ks + (kg * 64 + f * 8 + gr) * 272 + (cc + 2 * j) * 2;
                u32 bb[2];
                bb[0] = *(const u32*)(kb);
                bb[1] = *(const u32*)(kb + 16);
                mma_bf16(sacc[0][f], a[0], bb);
                mma_bf16(sacc[1][f], a[1], bb);
            }
        }
    }

    // epilogue: exp, store P, row sums
    u16* Pg = g_P + (size_t)tb * NN * NN;
#pragma unroll
    for (int mi = 0; mi < 2; mi++) {
        int r0 = qg * 32 + mi * 16 + gr;
        float rs0 = 0.0f, rs1 = 0.0f;
#pragma unroll
        for (int f = 0; f < 8; f++) {
            float p0 = fast_exp(sacc[mi][f][0] * 0.0625f);
            float p1 = fast_exp(sacc[mi][f][1] * 0.0625f);
            float p2 = fast_exp(sacc[mi][f][2] * 0.0625f);
            float p3 = fast_exp(sacc[mi][f][3] * 0.0625f);
            rs0 += p0 + p1; rs1 += p2 + p3;
            int col = k0 + kg * 64 + f * 8 + 2 * j;
            *(u32*)&Pg[(size_t)(q0 + r0) * NN + col]     = pack_bf16(p0, p1);
            *(u32*)&Pg[(size_t)(q0 + r0 + 8) * NN + col] = pack_bf16(p2, p3);
        }
        rs0 += __shfl_xor_sync(0xffffffffu, rs0, 1);
        rs0 += __shfl_xor_sync(0xffffffffu, rs0, 2);
        rs1 += __shfl_xor_sync(0xffffffffu, rs1, 1);
        rs1 += __shfl_xor_sync(0xffffffffu, rs1, 2);
        if (j == 0) {
            atomicAdd(&g_lacc[tb * NN + q0 + r0], rs0);
            atomicAdd(&g_lacc[tb * NN + q0 + r0 + 8], rs1);
        }
    }
}

// ---------------------------------------------------------------------------
// PV-kernel v3: 512 threads / 16 warps (4 per SMSP) to hide LDS->HMMA stalls.
// out = student + sum_t (P_t V_t) / (3 l_t). 3-stage cp.async.
// Grid (2 ctile(128), 8 qtile(128), 8 b). Warp tile 16q x 64c
// (qg = wid&7, cg = wid>>3).
// ---------------------------------------------------------------------------
#define PV_PSTG  34816                     // 128*272
#define PV_STAGE 69632                     // P + V per stage
#define PV_LACC  208896                    // 3 stages
#define PV_BYTES (PV_LACC + 3 * 128 * 4)

__global__ __launch_bounds__(512, 1) void pv_kernel(
    const float* __restrict__ student, float* __restrict__ out)
{
    extern __shared__ __align__(16) char smc[];
    float* laccS = (float*)(smc + PV_LACC);    // [3][128]
    const u32 smb = smem_u32(smc);

    const int tid  = threadIdx.x;
    const int wid  = tid >> 5, lane = tid & 31;
    const int gr   = lane >> 2, j = lane & 3;
    const int qg   = wid & 7, cg = wid >> 3;
    const int c0   = blockIdx.x * 128;
    const int q0   = blockIdx.y * 128;
    const int b    = blockIdx.z;
    const int r0   = qg * 16 + gr;             // fragment rows r0, r0+8

    // load lacc rows for this q-tile (384 floats)
    for (int i = tid; i < 384; i += 512) {
        int t = i >> 7, q = i & 127;
        laccS[i] = g_lacc[(t * 8 + b) * NN + q0 + q];
    }

    auto issue = [&](int i) {
        int t = i >> 3, kc = i & 7;
        const u16* Pg = g_P  + ((size_t)(t * 8 + b) * NN + q0) * NN + kc * 128;
        const u16* Vg = g_Vp + ((size_t)(t * 8 + b) * NC + c0) * NN + kc * 128;
        u32 base = smb + (u32)(i % 3) * PV_STAGE;
#pragma unroll
        for (int it = 0; it < 4; it++) {
            int idx = tid + 512 * it;
            int r = idx >> 4, u = (idx & 15) * 8;
            cp16(base + r * 272 + u * 2, &Pg[(size_t)r * NN + u]);
        }
#pragma unroll
        for (int it = 0; it < 4; it++) {
            int idx = tid + 512 * it;
            int r = idx >> 4, u = (idx & 15) * 8;
            cp16(base + PV_PSTG + r * 272 + u * 2, &Vg[(size_t)r * NN + u]);
        }
        cp_commit();
    };

    float oacc[8][4], pv[8][4];
#pragma unroll
    for (int f = 0; f < 8; f++)
#pragma unroll
        for (int e = 0; e < 4; e++) oacc[f][e] = 0.0f;

    issue(0); issue(1); issue(2);

    for (int i = 0; i < 24; i++) {
        if ((i & 7) == 0) {
#pragma unroll
            for (int f = 0; f < 8; f++)
#pragma unroll
                for (int e = 0; e < 4; e++) pv[f][e] = 0.0f;
        }

        if (i < 22)      { asm volatile("cp.async.wait_group 2;" ::: "memory"); }
        else if (i == 22){ asm volatile("cp.async.wait_group 1;" ::: "memory"); }
        else             { asm volatile("cp.async.wait_group 0;" ::: "memory"); }
        __syncthreads();

        const char* Ps = smc + (i % 3) * PV_STAGE;
        const char* Vs = Ps + PV_PSTG;

#pragma unroll 2
        for (int k0 = 0; k0 < 128; k0 += 16) {
            u32 a[4];
            {
                const char* base = Ps + r0 * 272 + (k0 + 2 * j) * 2;
                a[0] = *(const u32*)(base);
                a[1] = *(const u32*)(base + 8 * 272);
                a[2] = *(const u32*)(base + 16);
                a[3] = *(const u32*)(base + 8 * 272 + 16);
            }
#pragma unroll
            for (int f = 0; f < 8; f++) {
                const char* vb = Vs + (cg * 64 + f * 8 + gr) * 272 + (k0 + 2 * j) * 2;
                u32 bb[2];
                bb[0] = *(const u32*)(vb);
                bb[1] = *(const u32*)(vb + 16);
                mma_bf16(pv[f], a, bb);
            }
        }

        if ((i & 7) == 7) {
            int t = i >> 3;
            float inv0 = 1.0f / (3.0f * laccS[t * 128 + r0]);
            float inv1 = 1.0f / (3.0f * laccS[t * 128 + r0 + 8]);
#pragma unroll
            for (int f = 0; f < 8; f++) {
                oacc[f][0] += pv[f][0] * inv0;
                oacc[f][1] += pv[f][1] * inv0;
                oacc[f][2] += pv[f][2] * inv1;
                oacc[f][3] += pv[f][3] * inv1;
            }
        }
        __syncthreads();       // stage (i%3) consumed by all warps

        if (i <= 20) issue(i + 3);
    }

    // epilogue: transpose via smem, out = student + fused (coalesced)
    float* stg = (float*)smc;   // [128 c][132 q] f32, overlays stage buffers
#pragma unroll
    for (int f = 0; f < 8; f++) {
        int c = cg * 64 + f * 8 + 2 * j;
        stg[c * 132 + r0]           = oacc[f][0];
        stg[(c + 1) * 132 + r0]     = oacc[f][1];
        stg[c * 132 + r0 + 8]       = oacc[f][2];
        stg[(c + 1) * 132 + r0 + 8] = oacc[f][3];
    }
    __syncthreads();

    const float* stu  = student + ((size_t)b * NC + c0) * NN;
    float*       outp = out + ((size_t)b * NC + c0) * NN;
#pragma unroll
    for (int it = 0; it < 8; it++) {
        int idx = tid + 512 * it;          // 4096 float4 = 128c x 32 q4
        int c = idx >> 5, q4 = (idx & 31) * 4;
        size_t off = (size_t)c * NN + q0 + q4;
        float4 s4 = *(const float4*)&stg[c * 132 + q4];
        float4 bs = *(const float4*)&stu[off];
        float4 r;
        r.x = bs.x + s4.x; r.y = bs.y + s4.y;
        r.z = bs.z + s4.z; r.w = bs.w + s4.w;
        *(float4*)&outp[off] = r;
    }
}

// ---------------------------------------------------------------------------
extern "C" void kernel_launch(void* const* d_in, const int* in_sizes, int n_in,
                              void* d_out, int out_size)
{
    const float* student = (const float*)d_in[0];
    const float* t0 = (const float*)d_in[1];
    const float* t1 = (const float*)d_in[2];
    const float* t2 = (const float*)d_in[3];
    const float* Wq = (const float*)d_in[4];
    const float* bq = (const float*)d_in[5];
    const float* Wk = (const float*)d_in[6];
    const float* bk = (const float*)d_in[7];
    const float* Wv = (const float*)d_in[8];
    const float* bv = (const float*)d_in[9];
    float* out = (float*)d_out;

    zero_lacc_kernel<<<NT * NB, 1024>>>();

    dim3 pg(NN / 256, NC / 64, 7 * NB);
    proj_kernel<<<pg, 256>>>(Wq, bq, Wk, bk, Wv, bv, student, t0, t1, t2);

    cudaFuncSetAttribute(s_kernel, cudaFuncAttributeMaxDynamicSharedMemorySize,
                         S2_SMEM);
    s_kernel<<<dim3(NN / 256, NN / 128, NT * NB), 512, S2_SMEM>>>();

    cudaFuncSetAttribute(pv_kernel, cudaFuncAttributeMaxDynamicSharedMemorySize,
                         PV_BYTES);
    pv_kernel<<<dim3(NC / 128, NN / 128, NB), 512, PV_BYTES>>>(student, out);
}

// round 15
// speedup vs baseline: 1.0705x; 1.0705x over previous
#include <cuda_runtime.h>
#include <cuda_bf16.h>
#include <cstdint>

typedef uint32_t u32;
typedef uint16_t u16;

#define NB 8
#define NC 256
#define NN 1024
#define NT 3

// bf16 scratch: Q^T/K^T [.., n, c], V [.., c, n]
__device__ __align__(16) u16 g_QpT[NB * NN * NC];
__device__ __align__(16) u16 g_KpT[NT * NB * NN * NC];
__device__ __align__(16) u16 g_Vp [NT * NB * NC * NN];
// P = exp(S/16) bf16 [t*8+b][q][k], row sums
__device__ __align__(16) u16   g_P[(size_t)NT * NB * NN * NN];
__device__ float g_lacc[NT * NB * NN];

// ---------------- helpers ----------------
__device__ __forceinline__ u32 smem_u32(const void* p) {
    u32 a;
    asm("{ .reg .u64 t; cvta.to.shared.u64 t, %1; cvt.u32.u64 %0, t; }"
        : "=r"(a) : "l"(p));
    return a;
}
__device__ __forceinline__ void cp16(u32 dst, const void* src) {
    asm volatile("cp.async.cg.shared.global [%0], [%1], 16;"
                 :: "r"(dst), "l"(src) : "memory");
}
__device__ __forceinline__ void cp_commit() {
    asm volatile("cp.async.commit_group;" ::: "memory");
}
__device__ __forceinline__ void ldsm4(u32* r, u32 addr) {
    asm volatile("ldmatrix.sync.aligned.m8n8.x4.shared.b16 {%0,%1,%2,%3}, [%4];"
        : "=r"(r[0]), "=r"(r[1]), "=r"(r[2]), "=r"(r[3]) : "r"(addr));
}

__device__ __forceinline__ u32 to_tf32(float f) {
    u32 r; asm("cvt.rna.tf32.f32 %0, %1;" : "=r"(r) : "f"(f)); return r;
}
__device__ __forceinline__ float rnd_tf32(float f) { return __uint_as_float(to_tf32(f)); }

__device__ __forceinline__ u32 pack_bf16(float lo, float hi) {
    u32 r; asm("cvt.rn.bf16x2.f32 %0, %1, %2;" : "=r"(r) : "f"(hi), "f"(lo)); return r;
}
__device__ __forceinline__ u16 bf16_bits(float f) {
    u16 r; asm("cvt.rn.bf16.f32 %0, %1;" : "=h"(r) : "f"(f)); return r;
}

__device__ __forceinline__ void mma_tf32(float* d, const u32* a, const u32* b) {
    asm volatile(
        "mma.sync.aligned.m16n8k8.row.col.f32.tf32.tf32.f32 "
        "{%0,%1,%2,%3}, {%4,%5,%6,%7}, {%8,%9}, {%0,%1,%2,%3};"
        : "+f"(d[0]), "+f"(d[1]), "+f"(d[2]), "+f"(d[3])
        : "r"(a[0]), "r"(a[1]), "r"(a[2]), "r"(a[3]), "r"(b[0]), "r"(b[1]));
}
__device__ __forceinline__ void mma_bf16(float* d, const u32* a, const u32* b) {
    asm volatile(
        "mma.sync.aligned.m16n8k16.row.col.f32.bf16.bf16.f32 "
        "{%0,%1,%2,%3}, {%4,%5,%6,%7}, {%8,%9}, {%0,%1,%2,%3};"
        : "+f"(d[0]), "+f"(d[1]), "+f"(d[2]), "+f"(d[3])
        : "r"(a[0]), "r"(a[1]), "r"(a[2]), "r"(a[3]), "r"(b[0]), "r"(b[1]));
}

__device__ __forceinline__ float fast_exp(float x) {
    float t = fmaf(x, 1.4426950408889634f, 12582912.0f);
    float n = t - 12582912.0f;
    int   e = __float_as_int(t) << 23;
    float r = fmaf(x, 1.4426950408889634f, -n);
    float p = 1.3333558146e-3f;
    p = fmaf(p, r, 9.6181291076e-3f);
    p = fmaf(p, r, 5.5504108665e-2f);
    p = fmaf(p, r, 2.4022650696e-1f);
    p = fmaf(p, r, 6.9314718056e-1f);
    p = fmaf(p, r, 1.0f);
    return __int_as_float(__float_as_int(p) + e);
}

__global__ void zero_lacc_kernel() {
    g_lacc[blockIdx.x * 1024 + threadIdx.x] = 0.0f;
}

// ---------------------------------------------------------------------------
// Projection via tf32 mma (unchanged, proven): Out[o][n] = W @ X + b
// ---------------------------------------------------------------------------
#define PW_STR 36
#define PX_STR 264
#define PSM_BYTES (64 * PW_STR * 4 + 32 * PX_STR * 4)

__global__ __launch_bounds__(256) void proj_kernel(
    const float* __restrict__ Wq, const float* __restrict__ bq,
    const float* __restrict__ Wk, const float* __restrict__ bk,
    const float* __restrict__ Wv, const float* __restrict__ bv,
    const float* __restrict__ xs, const float* __restrict__ x0,
    const float* __restrict__ x1, const float* __restrict__ x2)
{
    __shared__ __align__(16) char psm[PSM_BYTES];
    float* Wsf = (float*)psm;
    float* Xsf = (float*)(psm + 64 * PW_STR * 4);
    u16*   stg = (u16*)psm;

    const int tid  = threadIdx.x;
    const int wid  = tid >> 5, lane = tid & 31;
    const int gr   = lane >> 2, j = lane & 3;
    const int ow   = wid & 1, nw = wid >> 1;
    const int n0   = blockIdx.x * 256;
    const int o0   = blockIdx.y * 64;
    const int z    = blockIdx.z;
    const int p    = z >> 3, b = z & 7;

    const float* W; const float* bias; const float* X;
    u16* dst; bool vmode;
    if (p == 0) {
        W = Wq; bias = bq; X = xs + (size_t)b * NC * NN;
        dst = g_QpT + (size_t)b * NN * NC; vmode = false;
    } else if (p <= 3) {
        W = Wk; bias = bk;
        const float* tf = (p == 1) ? x0 : ((p == 2) ? x1 : x2);
        X = tf + (size_t)b * NC * NN;
        dst = g_KpT + ((size_t)(p - 1) * NB + b) * NN * NC; vmode = false;
    } else {
        W = Wv; bias = bv;
        const float* tf = (p == 4) ? x0 : ((p == 5) ? x1 : x2);
        X = tf + (size_t)b * NC * NN;
        dst = g_Vp + ((size_t)(p - 4) * NB + b) * NC * NN; vmode = true;
    }

    float d[2][8][4];
#pragma unroll
    for (int mi = 0; mi < 2; mi++)
#pragma unroll
        for (int f = 0; f < 8; f++)
#pragma unroll
            for (int e = 0; e < 4; e++) d[mi][f][e] = 0.0f;

    for (int c0 = 0; c0 < NC; c0 += 32) {
        __syncthreads();
#pragma unroll
        for (int it = 0; it < 2; it++) {
            int idx = tid + 256 * it;
            int r = idx >> 3, c4 = (idx & 7) * 4;
            float4 w4 = *(const float4*)&W[(size_t)(o0 + r) * NC + c0 + c4];
            Wsf[r * PW_STR + c4 + 0] = rnd_tf32(w4.x);
            Wsf[r * PW_STR + c4 + 1] = rnd_tf32(w4.y);
            Wsf[r * PW_STR + c4 + 2] = rnd_tf32(w4.z);
            Wsf[r * PW_STR + c4 + 3] = rnd_tf32(w4.w);
        }
#pragma unroll
        for (int it = 0; it < 8; it++) {
            int idx = tid + 256 * it;
            int r = idx >> 6, n4 = (idx & 63) * 4;
            float4 x4 = *(const float4*)&X[(size_t)(c0 + r) * NN + n0 + n4];
            Xsf[r * PX_STR + n4 + 0] = rnd_tf32(x4.x);
            Xsf[r * PX_STR + n4 + 1] = rnd_tf32(x4.y);
            Xsf[r * PX_STR + n4 + 2] = rnd_tf32(x4.z);
            Xsf[r * PX_STR + n4 + 3] = rnd_tf32(x4.w);
        }
        __syncthreads();

#pragma unroll
        for (int kx = 0; kx < 4; kx++) {
            int k0 = kx * 8;
            u32 a[2][4];
#pragma unroll
            for (int mi = 0; mi < 2; mi++) {
                int row = ow * 32 + mi * 16 + gr;
                a[mi][0] = __float_as_uint(Wsf[row * PW_STR + k0 + j]);
                a[mi][1] = __float_as_uint(Wsf[(row + 8) * PW_STR + k0 + j]);
                a[mi][2] = __float_as_uint(Wsf[row * PW_STR + k0 + j + 4]);
                a[mi][3] = __float_as_uint(Wsf[(row + 8) * PW_STR + k0 + j + 4]);
            }
#pragma unroll
            for (int f = 0; f < 8; f++) {
                int n = nw * 64 + f * 8 + gr;
                u32 bb[2];
                bb[0] = __float_as_uint(Xsf[(k0 + j) * PX_STR + n]);
                bb[1] = __float_as_uint(Xsf[(k0 + j + 4) * PX_STR + n]);
                mma_tf32(d[0][f], a[0], bb);
                mma_tf32(d[1][f], a[1], bb);
            }
        }
    }

    float bi[2][2];
#pragma unroll
    for (int mi = 0; mi < 2; mi++) {
        bi[mi][0] = bias[o0 + ow * 32 + mi * 16 + gr];
        bi[mi][1] = bias[o0 + ow * 32 + mi * 16 + gr + 8];
    }

    if (vmode) {
#pragma unroll
        for (int mi = 0; mi < 2; mi++) {
            int row0 = o0 + ow * 32 + mi * 16 + gr;
#pragma unroll
            for (int f = 0; f < 8; f++) {
                int n = n0 + nw * 64 + f * 8 + 2 * j;
                *(u32*)&dst[(size_t)row0 * NN + n] =
                    pack_bf16(d[mi][f][0] + bi[mi][0], d[mi][f][1] + bi[mi][0]);
                *(u32*)&dst[(size_t)(row0 + 8) * NN + n] =
                    pack_bf16(d[mi][f][2] + bi[mi][1], d[mi][f][3] + bi[mi][1]);
            }
        }
    } else {
        __syncthreads();
#pragma unroll
        for (int mi = 0; mi < 2; mi++) {
            int row0 = ow * 32 + mi * 16 + gr;
#pragma unroll
            for (int f = 0; f < 8; f++) {
                int n = nw * 64 + f * 8 + 2 * j;
                stg[n * 72 + row0]           = bf16_bits(d[mi][f][0] + bi[mi][0]);
                stg[(n + 1) * 72 + row0]     = bf16_bits(d[mi][f][1] + bi[mi][0]);
                stg[n * 72 + row0 + 8]       = bf16_bits(d[mi][f][2] + bi[mi][1]);
                stg[(n + 1) * 72 + row0 + 8] = bf16_bits(d[mi][f][3] + bi[mi][1]);
            }
        }
        __syncthreads();
#pragma unroll
        for (int it = 0; it < 8; it++) {
            int idx = tid + 256 * it;
            int n = idx >> 3, u = (idx & 7) * 8;
            *(uint4*)&dst[(size_t)(n0 + n) * NC + o0 + u] = *(const uint4*)&stg[n * 72 + u];
        }
    }
}

// ---------------------------------------------------------------------------
// S-kernel: P = exp((Q K^T)/16), c-reduction in two cp.async-pipelined halves.
// Grid (4 ktile(256), 8 qtile(128), 24 tb), 512 threads. ldmatrix fragments.
// ---------------------------------------------------------------------------
#define S2_K     34816                     // Q part size (128*272)
#define S2_STAGE 104448                    // Q + K per stage
#define S2_SMEM  208896

__global__ __launch_bounds__(512, 1) void s_kernel()
{
    extern __shared__ __align__(16) char smc[];
    const u32 smb = smem_u32(smc);

    const int tid  = threadIdx.x;
    const int wid  = tid >> 5, lane = tid & 31;
    const int gr   = lane >> 2, j = lane & 3;
    const int qg   = wid & 3, kg = wid >> 2;
    const int k0t  = blockIdx.x * 256;
    const int q0   = blockIdx.y * 128;
    const int tb   = blockIdx.z;
    const int b    = tb & 7;

    const u16* Qg = g_QpT + ((size_t)b * NN + q0) * NC;
    const u16* Kg = g_KpT + ((size_t)tb * NN + k0t) * NC;

    // per-lane ldmatrix offsets (byte): A rows 16, m0/m1 rows, m2/m3 k+8
    const int lrow = (lane & 7) + ((lane >> 3) & 1) * 8;
    const u32 aoff0 = (u32)(qg * 32 + lrow) * 272 + ((lane >> 4) & 1) * 16;
    const u32 aoff1 = aoff0 + 16 * 272;
    // B: lanes 0-15 -> n rows 0-7 @k0 / @k0+8; 16-31 -> n rows 8-15
    const u32 boff  = (u32)(kg * 64 + (lane & 7) + ((lane >> 4) & 1) * 8) * 272
                      + ((lane >> 3) & 1) * 16;

    auto issueS = [&](int h) {
        u32 base = smb + (u32)h * S2_STAGE;
#pragma unroll
        for (int it = 0; it < 4; it++) {
            int idx = tid + 512 * it;
            int r = idx >> 4, u = (idx & 15) * 8;
            cp16(base + r * 272 + u * 2, &Qg[(size_t)r * NC + h * 128 + u]);
        }
#pragma unroll
        for (int it = 0; it < 8; it++) {
            int idx = tid + 512 * it;
            int r = idx >> 4, u = (idx & 15) * 8;
            cp16(base + S2_K + r * 272 + u * 2, &Kg[(size_t)r * NC + h * 128 + u]);
        }
        cp_commit();
    };

    issueS(0);
    issueS(1);

    float sacc[2][8][4];
#pragma unroll
    for (int mi = 0; mi < 2; mi++)
#pragma unroll
        for (int f = 0; f < 8; f++)
#pragma unroll
            for (int e = 0; e < 4; e++) sacc[mi][f][e] = 0.0f;

#pragma unroll
    for (int h = 0; h < 2; h++) {
        if (h == 0) { asm volatile("cp.async.wait_group 1;" ::: "memory"); }
        else        { asm volatile("cp.async.wait_group 0;" ::: "memory"); }
        __syncthreads();

        const u32 Qs = smb + (u32)h * S2_STAGE;
        const u32 Ks = Qs + S2_K;

#pragma unroll 4
        for (int cc = 0; cc < 128; cc += 16) {
            u32 a0[4], a1[4];
            ldsm4(a0, Qs + aoff0 + cc * 2);
            ldsm4(a1, Qs + aoff1 + cc * 2);
#pragma unroll
            for (int fp = 0; fp < 4; fp++) {
                u32 bb[4];
                ldsm4(bb, Ks + boff + fp * (16 * 272) + cc * 2);
                mma_bf16(sacc[0][2 * fp],     a0, bb);
                mma_bf16(sacc[0][2 * fp + 1], a0, bb + 2);
                mma_bf16(sacc[1][2 * fp],     a1, bb);
                mma_bf16(sacc[1][2 * fp + 1], a1, bb + 2);
            }
        }
    }

    // epilogue: exp, store P, row sums
    u16* Pg = g_P + (size_t)tb * NN * NN;
#pragma unroll
    for (int mi = 0; mi < 2; mi++) {
        int r0 = qg * 32 + mi * 16 + gr;
        float rs0 = 0.0f, rs1 = 0.0f;
#pragma unroll
        for (int f = 0; f < 8; f++) {
            float p0 = fast_exp(sacc[mi][f][0] * 0.0625f);
            float p1 = fast_exp(sacc[mi][f][1] * 0.0625f);
            float p2 = fast_exp(sacc[mi][f][2] * 0.0625f);
            float p3 = fast_exp(sacc[mi][f][3] * 0.0625f);
            rs0 += p0 + p1; rs1 += p2 + p3;
            int col = k0t + kg * 64 + f * 8 + 2 * j;
            *(u32*)&Pg[(size_t)(q0 + r0) * NN + col]     = pack_bf16(p0, p1);
            *(u32*)&Pg[(size_t)(q0 + r0 + 8) * NN + col] = pack_bf16(p2, p3);
        }
        rs0 += __shfl_xor_sync(0xffffffffu, rs0, 1);
        rs0 += __shfl_xor_sync(0xffffffffu, rs0, 2);
        rs1 += __shfl_xor_sync(0xffffffffu, rs1, 1);
        rs1 += __shfl_xor_sync(0xffffffffu, rs1, 2);
        if (j == 0) {
            atomicAdd(&g_lacc[tb * NN + q0 + r0], rs0);
            atomicAdd(&g_lacc[tb * NN + q0 + r0 + 8], rs1);
        }
    }
}

// ---------------------------------------------------------------------------
// PV-kernel: out = student + sum_t (P_t V_t) / (3 l_t). 3-stage cp.async,
// 256 threads / 8 warps (proven best), ldmatrix fragments.
// Grid (2 ctile(128), 8 qtile(128), 8 b). Warp tile 32q x 64c.
// ---------------------------------------------------------------------------
#define PV_PSTG  34816                     // 128*272
#define PV_STAGE 69632                     // P + V per stage
#define PV_LACC  208896                    // 3 stages
#define PV_BYTES (PV_LACC + 3 * 128 * 4)

__global__ __launch_bounds__(256, 1) void pv_kernel(
    const float* __restrict__ student, float* __restrict__ out)
{
    extern __shared__ __align__(16) char smc[];
    float* laccS = (float*)(smc + PV_LACC);    // [3][128]
    const u32 smb = smem_u32(smc);

    const int tid  = threadIdx.x;
    const int wid  = tid >> 5, lane = tid & 31;
    const int gr   = lane >> 2, j = lane & 3;
    const int qg   = wid & 3, cg = wid >> 2;
    const int c0   = blockIdx.x * 128;
    const int q0   = blockIdx.y * 128;
    const int b    = blockIdx.z;

    const int lrow = (lane & 7) + ((lane >> 3) & 1) * 8;
    const u32 aoff0 = (u32)(qg * 32 + lrow) * 272 + ((lane >> 4) & 1) * 16;
    const u32 aoff1 = aoff0 + 16 * 272;
    const u32 boff  = (u32)(cg * 64 + (lane & 7) + ((lane >> 4) & 1) * 8) * 272
                      + ((lane >> 3) & 1) * 16;

    // load lacc rows for this q-tile (384 floats)
    for (int i = tid; i < 384; i += 256) {
        int t = i >> 7, q = i & 127;
        laccS[i] = g_lacc[(t * 8 + b) * NN + q0 + q];
    }

    auto issue = [&](int i) {
        int t = i >> 3, kc = i & 7;
        const u16* Pg = g_P  + ((size_t)(t * 8 + b) * NN + q0) * NN + kc * 128;
        const u16* Vg = g_Vp + ((size_t)(t * 8 + b) * NC + c0) * NN + kc * 128;
        u32 base = smb + (u32)(i % 3) * PV_STAGE;
#pragma unroll
        for (int it = 0; it < 8; it++) {
            int idx = tid + 256 * it;
            int r = idx >> 4, u = (idx & 15) * 8;
            cp16(base + r * 272 + u * 2, &Pg[(size_t)r * NN + u]);
        }
#pragma unroll
        for (int it = 0; it < 8; it++) {
            int idx = tid + 256 * it;
            int r = idx >> 4, u = (idx & 15) * 8;
            cp16(base + PV_PSTG + r * 272 + u * 2, &Vg[(size_t)r * NN + u]);
        }
        cp_commit();
    };

    float oacc[2][8][4], pv[2][8][4];
#pragma unroll
    for (int mi = 0; mi < 2; mi++)
#pragma unroll
        for (int f = 0; f < 8; f++)
#pragma unroll
            for (int e = 0; e < 4; e++) oacc[mi][f][e] = 0.0f;

    issue(0); issue(1); issue(2);

    for (int i = 0; i < 24; i++) {
        if ((i & 7) == 0) {
#pragma unroll
            for (int mi = 0; mi < 2; mi++)
#pragma unroll
                for (int f = 0; f < 8; f++)
#pragma unroll
                    for (int e = 0; e < 4; e++) pv[mi][f][e] = 0.0f;
        }

        if (i < 22)      { asm volatile("cp.async.wait_group 2;" ::: "memory"); }
        else if (i == 22){ asm volatile("cp.async.wait_group 1;" ::: "memory"); }
        else             { asm volatile("cp.async.wait_group 0;" ::: "memory"); }
        __syncthreads();

        const u32 Ps = smb + (u32)(i % 3) * PV_STAGE;
        const u32 Vs = Ps + PV_PSTG;

#pragma unroll 2
        for (int k0 = 0; k0 < 128; k0 += 16) {
            u32 a0[4], a1[4];
            ldsm4(a0, Ps + aoff0 + k0 * 2);
            ldsm4(a1, Ps + aoff1 + k0 * 2);
#pragma unroll
            for (int fp = 0; fp < 4; fp++) {
                u32 bb[4];
                ldsm4(bb, Vs + boff + fp * (16 * 272) + k0 * 2);
                mma_bf16(pv[0][2 * fp],     a0, bb);
                mma_bf16(pv[0][2 * fp + 1], a0, bb + 2);
                mma_bf16(pv[1][2 * fp],     a1, bb);
                mma_bf16(pv[1][2 * fp + 1], a1, bb + 2);
            }
        }

        if ((i & 7) == 7) {
            int t = i >> 3;
#pragma unroll
            for (int mi = 0; mi < 2; mi++) {
                int r0 = qg * 32 + mi * 16 + gr;
                float inv0 = 1.0f / (3.0f * laccS[t * 128 + r0]);
                float inv1 = 1.0f / (3.0f * laccS[t * 128 + r0 + 8]);
#pragma unroll
                for (int f = 0; f < 8; f++) {
                    oacc[mi][f][0] += pv[mi][f][0] * inv0;
                    oacc[mi][f][1] += pv[mi][f][1] * inv0;
                    oacc[mi][f][2] += pv[mi][f][2] * inv1;
                    oacc[mi][f][3] += pv[mi][f][3] * inv1;
                }
            }
        }
        __syncthreads();       // stage (i%3) consumed by all warps

        if (i <= 20) issue(i + 3);
    }

    // epilogue: transpose via smem, out = student + fused (coalesced)
    float* stg = (float*)smc;   // [128 c][132 q] f32, overlays stage buffers
#pragma unroll
    for (int mi = 0; mi < 2; mi++) {
        int r0 = qg * 32 + mi * 16 + gr;
#pragma unroll
        for (int f = 0; f < 8; f++) {
            int c = cg * 64 + f * 8 + 2 * j;
            stg[c * 132 + r0]           = oacc[mi][f][0];
            stg[(c + 1) * 132 + r0]     = oacc[mi][f][1];
            stg[c * 132 + r0 + 8]       = oacc[mi][f][2];
            stg[(c + 1) * 132 + r0 + 8] = oacc[mi][f][3];
        }
    }
    __syncthreads();

    const float* stu  = student + ((size_t)b * NC + c0) * NN;
    float*       outp = out + ((size_t)b * NC + c0) * NN;
#pragma unroll
    for (int it = 0; it < 16; it++) {
        int idx = tid + 256 * it;          // 4096 float4 = 128c x 32 q4
        int c = idx >> 5, q4 = (idx & 31) * 4;
        size_t off = (size_t)c * NN + q0 + q4;
        float4 s4 = *(const float4*)&stg[c * 132 + q4];
        float4 bs = *(const float4*)&stu[off];
        float4 r;
        r.x = bs.x + s4.x; r.y = bs.y + s4.y;
        r.z = bs.z + s4.z; r.w = bs.w + s4.w;
        *(float4*)&outp[off] = r;
    }
}

// ---------------------------------------------------------------------------
extern "C" void kernel_launch(void* const* d_in, const int* in_sizes, int n_in,
                              void* d_out, int out_size)
{
    const float* student = (const float*)d_in[0];
    const float* t0 = (const float*)d_in[1];
    const float* t1 = (const float*)d_in[2];
    const float* t2 = (const float*)d_in[3];
    const float* Wq = (const float*)d_in[4];
    const float* bq = (const float*)d_in[5];
    const float* Wk = (const float*)d_in[6];
    const float* bk = (const float*)d_in[7];
    const float* Wv = (const float*)d_in[8];
    const float* bv = (const float*)d_in[9];
    float* out = (float*)d_out;

    zero_lacc_kernel<<<NT * NB, 1024>>>();

    dim3 pg(NN / 256, NC / 64, 7 * NB);
    proj_kernel<<<pg, 256>>>(Wq, bq, Wk, bk, Wv, bv, student, t0, t1, t2);

    cudaFuncSetAttribute(s_kernel, cudaFuncAttributeMaxDynamicSharedMemorySize,
                         S2_SMEM);
    s_kernel<<<dim3(NN / 256, NN / 128, NT * NB), 512, S2_SMEM>>>();

    cudaFuncSetAttribute(pv_kernel, cudaFuncAttributeMaxDynamicSharedMemorySize,
                         PV_BYTES);
    pv_kernel<<<dim3(NC / 128, NN / 128, NB), 256, PV_BYTES>>>(student, out);
}

// round 16
// speedup vs baseline: 1.2024x; 1.1232x over previous
#include <cuda_runtime.h>
#include <cuda_bf16.h>
#include <cstdint>

typedef uint32_t u32;
typedef uint16_t u16;

#define NB 8
#define NC 256
#define NN 1024
#define NT 3

// bf16 scratch: Q^T/K^T [.., n, c], V [.., c, n]
__device__ __align__(16) u16 g_QpT[NB * NN * NC];
__device__ __align__(16) u16 g_KpT[NT * NB * NN * NC];
__device__ __align__(16) u16 g_Vp [NT * NB * NC * NN];
// P = exp(S/16) bf16 [t*8+b][q][k], row sums
__device__ __align__(16) u16   g_P[(size_t)NT * NB * NN * NN];
__device__ float g_lacc[NT * NB * NN];

// ---------------- helpers ----------------
__device__ __forceinline__ u32 smem_u32(const void* p) {
    u32 a;
    asm("{ .reg .u64 t; cvta.to.shared.u64 t, %1; cvt.u32.u64 %0, t; }"
        : "=r"(a) : "l"(p));
    return a;
}
__device__ __forceinline__ void cp16(u32 dst, const void* src) {
    asm volatile("cp.async.cg.shared.global [%0], [%1], 16;"
                 :: "r"(dst), "l"(src) : "memory");
}
__device__ __forceinline__ void cp_commit() {
    asm volatile("cp.async.commit_group;" ::: "memory");
}
__device__ __forceinline__ void ldsm4(u32* r, u32 addr) {
    asm volatile("ldmatrix.sync.aligned.m8n8.x4.shared.b16 {%0,%1,%2,%3}, [%4];"
        : "=r"(r[0]), "=r"(r[1]), "=r"(r[2]), "=r"(r[3]) : "r"(addr));
}

__device__ __forceinline__ u32 pack_bf16(float lo, float hi) {
    u32 r; asm("cvt.rn.bf16x2.f32 %0, %1, %2;" : "=r"(r) : "f"(hi), "f"(lo)); return r;
}
__device__ __forceinline__ u16 bf16_bits(float f) {
    u16 r; asm("cvt.rn.bf16.f32 %0, %1;" : "=h"(r) : "f"(f)); return r;
}

__device__ __forceinline__ void mma_bf16(float* d, const u32* a, const u32* b) {
    asm volatile(
        "mma.sync.aligned.m16n8k16.row.col.f32.bf16.bf16.f32 "
        "{%0,%1,%2,%3}, {%4,%5,%6,%7}, {%8,%9}, {%0,%1,%2,%3};"
        : "+f"(d[0]), "+f"(d[1]), "+f"(d[2]), "+f"(d[3])
        : "r"(a[0]), "r"(a[1]), "r"(a[2]), "r"(a[3]), "r"(b[0]), "r"(b[1]));
}

__device__ __forceinline__ float fast_exp(float x) {
    float t = fmaf(x, 1.4426950408889634f, 12582912.0f);
    float n = t - 12582912.0f;
    int   e = __float_as_int(t) << 23;
    float r = fmaf(x, 1.4426950408889634f, -n);
    float p = 1.3333558146e-3f;
    p = fmaf(p, r, 9.6181291076e-3f);
    p = fmaf(p, r, 5.5504108665e-2f);
    p = fmaf(p, r, 2.4022650696e-1f);
    p = fmaf(p, r, 6.9314718056e-1f);
    p = fmaf(p, r, 1.0f);
    return __int_as_float(__float_as_int(p) + e);
}

__global__ void zero_lacc_kernel() {
    g_lacc[blockIdx.x * 1024 + threadIdx.x] = 0.0f;
}

// ---------------------------------------------------------------------------
// Projection via bf16 mma (m16n8k16): Out[o][n] = W @ X + b.
// W in smem bf16 [64][40] rows; X pre-packed k-pairs: Xp[c/2][n] u32.
// CTA tile 64o x 256n, 8 warps (ow = wid&1, nw = wid>>1), warp 32o x 64n.
// Grid: (NN/256, NC/64, 7*8)
// ---------------------------------------------------------------------------
#define PW_STR 40                          // u16 stride (80 B rows)
#define PX_STR 264                         // u32 stride (1056 B rows)
#define PW_BYTES (64 * PW_STR * 2)         // 5120
#define PX_BYTES (16 * PX_STR * 4)         // 16896
#define PSM_BYTES (256 * 72 * 2)           // 36864 (stage overlay is largest)

__global__ __launch_bounds__(256) void proj_kernel(
    const float* __restrict__ Wq, const float* __restrict__ bq,
    const float* __restrict__ Wk, const float* __restrict__ bk,
    const float* __restrict__ Wv, const float* __restrict__ bv,
    const float* __restrict__ xs, const float* __restrict__ x0,
    const float* __restrict__ x1, const float* __restrict__ x2)
{
    __shared__ __align__(16) char psm[PSM_BYTES];
    u16* Wsb = (u16*)psm;                       // [64][40] bf16
    u32* Xp  = (u32*)(psm + PW_BYTES);          // [16][264] bf16x2 pairs
    u16* stg = (u16*)psm;                       // overlay: [256 n][72 o] bf16

    const int tid  = threadIdx.x;
    const int wid  = tid >> 5, lane = tid & 31;
    const int gr   = lane >> 2, j = lane & 3;
    const int ow   = wid & 1, nw = wid >> 1;
    const int n0   = blockIdx.x * 256;
    const int o0   = blockIdx.y * 64;
    const int z    = blockIdx.z;
    const int p    = z >> 3, b = z & 7;

    const float* W; const float* bias; const float* X;
    u16* dst; bool vmode;
    if (p == 0) {
        W = Wq; bias = bq; X = xs + (size_t)b * NC * NN;
        dst = g_QpT + (size_t)b * NN * NC; vmode = false;
    } else if (p <= 3) {
        W = Wk; bias = bk;
        const float* tf = (p == 1) ? x0 : ((p == 2) ? x1 : x2);
        X = tf + (size_t)b * NC * NN;
        dst = g_KpT + ((size_t)(p - 1) * NB + b) * NN * NC; vmode = false;
    } else {
        W = Wv; bias = bv;
        const float* tf = (p == 4) ? x0 : ((p == 5) ? x1 : x2);
        X = tf + (size_t)b * NC * NN;
        dst = g_Vp + ((size_t)(p - 4) * NB + b) * NC * NN; vmode = true;
    }

    float d[2][8][4];
#pragma unroll
    for (int mi = 0; mi < 2; mi++)
#pragma unroll
        for (int f = 0; f < 8; f++)
#pragma unroll
            for (int e = 0; e < 4; e++) d[mi][f][e] = 0.0f;

    for (int c0 = 0; c0 < NC; c0 += 32) {
        __syncthreads();
        // W chunk 64o x 32c -> bf16 [64][40]
#pragma unroll
        for (int it = 0; it < 2; it++) {
            int idx = tid + 256 * it;              // 512 quads
            int r = idx >> 3, c4 = (idx & 7) * 4;
            float4 w4 = *(const float4*)&W[(size_t)(o0 + r) * NC + c0 + c4];
            uint2 pk;
            pk.x = pack_bf16(w4.x, w4.y);
            pk.y = pack_bf16(w4.z, w4.w);
            *(uint2*)&Wsb[r * PW_STR + c4] = pk;
        }
        // X chunk 32c x 256n -> packed pairs Xp[16][264]
#pragma unroll
        for (int it = 0; it < 4; it++) {
            int idx = tid + 256 * it;              // 1024 quads (16 rows x 64)
            int rp = idx >> 6, n4 = (idx & 63) * 4;
            const float* xr0 = &X[(size_t)(c0 + 2 * rp) * NN + n0 + n4];
            float4 xa = *(const float4*)xr0;
            float4 xb = *(const float4*)(xr0 + NN);
            uint4 pk;
            pk.x = pack_bf16(xa.x, xb.x);
            pk.y = pack_bf16(xa.y, xb.y);
            pk.z = pack_bf16(xa.z, xb.z);
            pk.w = pack_bf16(xa.w, xb.w);
            *(uint4*)&Xp[rp * PX_STR + n4] = pk;
        }
        __syncthreads();

#pragma unroll
        for (int kx = 0; kx < 2; kx++) {           // two k16 steps
            u32 a[2][4];
#pragma unroll
            for (int mi = 0; mi < 2; mi++) {
                int row = ow * 32 + mi * 16 + gr;
                const u16* base = &Wsb[row * PW_STR + kx * 16 + 2 * j];
                a[mi][0] = *(const u32*)(base);
                a[mi][1] = *(const u32*)(base + 8 * PW_STR);
                a[mi][2] = *(const u32*)(base + 8);            // k+8 (16 B)
                a[mi][3] = *(const u32*)(base + 8 * PW_STR + 8);
            }
#pragma unroll
            for (int f = 0; f < 8; f++) {
                int n = nw * 64 + f * 8 + gr;
                u32 bb[2];
                bb[0] = Xp[(kx * 8 + j) * PX_STR + n];
                bb[1] = Xp[(kx * 8 + 4 + j) * PX_STR + n];
                mma_bf16(d[0][f], a[0], bb);
                mma_bf16(d[1][f], a[1], bb);
            }
        }
    }

    float bi[2][2];
#pragma unroll
    for (int mi = 0; mi < 2; mi++) {
        bi[mi][0] = bias[o0 + ow * 32 + mi * 16 + gr];
        bi[mi][1] = bias[o0 + ow * 32 + mi * 16 + gr + 8];
    }

    if (vmode) {
#pragma unroll
        for (int mi = 0; mi < 2; mi++) {
            int row0 = o0 + ow * 32 + mi * 16 + gr;
#pragma unroll
            for (int f = 0; f < 8; f++) {
                int n = n0 + nw * 64 + f * 8 + 2 * j;
                *(u32*)&dst[(size_t)row0 * NN + n] =
                    pack_bf16(d[mi][f][0] + bi[mi][0], d[mi][f][1] + bi[mi][0]);
                *(u32*)&dst[(size_t)(row0 + 8) * NN + n] =
                    pack_bf16(d[mi][f][2] + bi[mi][1], d[mi][f][3] + bi[mi][1]);
            }
        }
    } else {
        __syncthreads();
#pragma unroll
        for (int mi = 0; mi < 2; mi++) {
            int row0 = ow * 32 + mi * 16 + gr;
#pragma unroll
            for (int f = 0; f < 8; f++) {
                int n = nw * 64 + f * 8 + 2 * j;
                stg[n * 72 + row0]           = bf16_bits(d[mi][f][0] + bi[mi][0]);
                stg[(n + 1) * 72 + row0]     = bf16_bits(d[mi][f][1] + bi[mi][0]);
                stg[n * 72 + row0 + 8]       = bf16_bits(d[mi][f][2] + bi[mi][1]);
                stg[(n + 1) * 72 + row0 + 8] = bf16_bits(d[mi][f][3] + bi[mi][1]);
            }
        }
        __syncthreads();
#pragma unroll
        for (int it = 0; it < 8; it++) {
            int idx = tid + 256 * it;
            int n = idx >> 3, u = (idx & 7) * 8;
            *(uint4*)&dst[(size_t)(n0 + n) * NC + o0 + u] = *(const uint4*)&stg[n * 72 + u];
        }
    }
}

// ---------------------------------------------------------------------------
// S-kernel: P = exp((Q K^T)/16), c-reduction in two cp.async-pipelined halves.
// Grid (4 ktile(256), 8 qtile(128), 24 tb), 512 threads. ldmatrix fragments.
// ---------------------------------------------------------------------------
#define S2_K     34816                     // Q part size (128*272)
#define S2_STAGE 104448                    // Q + K per stage
#define S2_SMEM  208896

__global__ __launch_bounds__(512, 1) void s_kernel()
{
    extern __shared__ __align__(16) char smc[];
    const u32 smb = smem_u32(smc);

    const int tid  = threadIdx.x;
    const int wid  = tid >> 5, lane = tid & 31;
    const int gr   = lane >> 2, j = lane & 3;
    const int qg   = wid & 3, kg = wid >> 2;
    const int k0t  = blockIdx.x * 256;
    const int q0   = blockIdx.y * 128;
    const int tb   = blockIdx.z;
    const int b    = tb & 7;

    const u16* Qg = g_QpT + ((size_t)b * NN + q0) * NC;
    const u16* Kg = g_KpT + ((size_t)tb * NN + k0t) * NC;

    const int lrow = (lane & 7) + ((lane >> 3) & 1) * 8;
    const u32 aoff0 = (u32)(qg * 32 + lrow) * 272 + ((lane >> 4) & 1) * 16;
    const u32 aoff1 = aoff0 + 16 * 272;
    const u32 boff  = (u32)(kg * 64 + (lane & 7) + ((lane >> 4) & 1) * 8) * 272
                      + ((lane >> 3) & 1) * 16;

    auto issueS = [&](int h) {
        u32 base = smb + (u32)h * S2_STAGE;
#pragma unroll
        for (int it = 0; it < 4; it++) {
            int idx = tid + 512 * it;
            int r = idx >> 4, u = (idx & 15) * 8;
            cp16(base + r * 272 + u * 2, &Qg[(size_t)r * NC + h * 128 + u]);
        }
#pragma unroll
        for (int it = 0; it < 8; it++) {
            int idx = tid + 512 * it;
            int r = idx >> 4, u = (idx & 15) * 8;
            cp16(base + S2_K + r * 272 + u * 2, &Kg[(size_t)r * NC + h * 128 + u]);
        }
        cp_commit();
    };

    issueS(0);
    issueS(1);

    float sacc[2][8][4];
#pragma unroll
    for (int mi = 0; mi < 2; mi++)
#pragma unroll
        for (int f = 0; f < 8; f++)
#pragma unroll
            for (int e = 0; e < 4; e++) sacc[mi][f][e] = 0.0f;

#pragma unroll
    for (int h = 0; h < 2; h++) {
        if (h == 0) { asm volatile("cp.async.wait_group 1;" ::: "memory"); }
        else        { asm volatile("cp.async.wait_group 0;" ::: "memory"); }
        __syncthreads();

        const u32 Qs = smb + (u32)h * S2_STAGE;
        const u32 Ks = Qs + S2_K;

#pragma unroll 4
        for (int cc = 0; cc < 128; cc += 16) {
            u32 a0[4], a1[4];
            ldsm4(a0, Qs + aoff0 + cc * 2);
            ldsm4(a1, Qs + aoff1 + cc * 2);
#pragma unroll
            for (int fp = 0; fp < 4; fp++) {
                u32 bb[4];
                ldsm4(bb, Ks + boff + fp * (16 * 272) + cc * 2);
                mma_bf16(sacc[0][2 * fp],     a0, bb);
                mma_bf16(sacc[0][2 * fp + 1], a0, bb + 2);
                mma_bf16(sacc[1][2 * fp],     a1, bb);
                mma_bf16(sacc[1][2 * fp + 1], a1, bb + 2);
            }
        }
    }

    // epilogue: exp, store P, row sums
    u16* Pg = g_P + (size_t)tb * NN * NN;
#pragma unroll
    for (int mi = 0; mi < 2; mi++) {
        int r0 = qg * 32 + mi * 16 + gr;
        float rs0 = 0.0f, rs1 = 0.0f;
#pragma unroll
        for (int f = 0; f < 8; f++) {
            float p0 = fast_exp(sacc[mi][f][0] * 0.0625f);
            float p1 = fast_exp(sacc[mi][f][1] * 0.0625f);
            float p2 = fast_exp(sacc[mi][f][2] * 0.0625f);
            float p3 = fast_exp(sacc[mi][f][3] * 0.0625f);
            rs0 += p0 + p1; rs1 += p2 + p3;
            int col = k0t + kg * 64 + f * 8 + 2 * j;
            *(u32*)&Pg[(size_t)(q0 + r0) * NN + col]     = pack_bf16(p0, p1);
            *(u32*)&Pg[(size_t)(q0 + r0 + 8) * NN + col] = pack_bf16(p2, p3);
        }
        rs0 += __shfl_xor_sync(0xffffffffu, rs0, 1);
        rs0 += __shfl_xor_sync(0xffffffffu, rs0, 2);
        rs1 += __shfl_xor_sync(0xffffffffu, rs1, 1);
        rs1 += __shfl_xor_sync(0xffffffffu, rs1, 2);
        if (j == 0) {
            atomicAdd(&g_lacc[tb * NN + q0 + r0], rs0);
            atomicAdd(&g_lacc[tb * NN + q0 + r0 + 8], rs1);
        }
    }
}

// ---------------------------------------------------------------------------
// PV-kernel: out = student + sum_t (P_t V_t) / (3 l_t). 3-stage cp.async,
// 256 threads / 8 warps, ldmatrix fragments.
// Grid (2 ctile(128), 8 qtile(128), 8 b). Warp tile 32q x 64c.
// ---------------------------------------------------------------------------
#define PV_PSTG  34816                     // 128*272
#define PV_STAGE 69632                     // P + V per stage
#define PV_LACC  208896                    // 3 stages
#define PV_BYTES (PV_LACC + 3 * 128 * 4)

__global__ __launch_bounds__(256, 1) void pv_kernel(
    const float* __restrict__ student, float* __restrict__ out)
{
    extern __shared__ __align__(16) char smc[];
    float* laccS = (float*)(smc + PV_LACC);    // [3][128]
    const u32 smb = smem_u32(smc);

    const int tid  = threadIdx.x;
    const int wid  = tid >> 5, lane = tid & 31;
    const int gr   = lane >> 2, j = lane & 3;
    const int qg   = wid & 3, cg = wid >> 2;
    const int c0   = blockIdx.x * 128;
    const int q0   = blockIdx.y * 128;
    const int b    = blockIdx.z;

    const int lrow = (lane & 7) + ((lane >> 3) & 1) * 8;
    const u32 aoff0 = (u32)(qg * 32 + lrow) * 272 + ((lane >> 4) & 1) * 16;
    const u32 aoff1 = aoff0 + 16 * 272;
    const u32 boff  = (u32)(cg * 64 + (lane & 7) + ((lane >> 4) & 1) * 8) * 272
                      + ((lane >> 3) & 1) * 16;

    // load lacc rows for this q-tile (384 floats)
    for (int i = tid; i < 384; i += 256) {
        int t = i >> 7, q = i & 127;
        laccS[i] = g_lacc[(t * 8 + b) * NN + q0 + q];
    }

    auto issue = [&](int i) {
        int t = i >> 3, kc = i & 7;
        const u16* Pg = g_P  + ((size_t)(t * 8 + b) * NN + q0) * NN + kc * 128;
        const u16* Vg = g_Vp + ((size_t)(t * 8 + b) * NC + c0) * NN + kc * 128;
        u32 base = smb + (u32)(i % 3) * PV_STAGE;
#pragma unroll
        for (int it = 0; it < 8; it++) {
            int idx = tid + 256 * it;
            int r = idx >> 4, u = (idx & 15) * 8;
            cp16(base + r * 272 + u * 2, &Pg[(size_t)r * NN + u]);
        }
#pragma unroll
        for (int it = 0; it < 8; it++) {
            int idx = tid + 256 * it;
            int r = idx >> 4, u = (idx & 15) * 8;
            cp16(base + PV_PSTG + r * 272 + u * 2, &Vg[(size_t)r * NN + u]);
        }
        cp_commit();
    };

    float oacc[2][8][4], pv[2][8][4];
#pragma unroll
    for (int mi = 0; mi < 2; mi++)
#pragma unroll
        for (int f = 0; f < 8; f++)
#pragma unroll
            for (int e = 0; e < 4; e++) oacc[mi][f][e] = 0.0f;

    issue(0); issue(1); issue(2);

    for (int i = 0; i < 24; i++) {
        if ((i & 7) == 0) {
#pragma unroll
            for (int mi = 0; mi < 2; mi++)
#pragma unroll
                for (int f = 0; f < 8; f++)
#pragma unroll
                    for (int e = 0; e < 4; e++) pv[mi][f][e] = 0.0f;
        }

        if (i < 22)      { asm volatile("cp.async.wait_group 2;" ::: "memory"); }
        else if (i == 22){ asm volatile("cp.async.wait_group 1;" ::: "memory"); }
        else             { asm volatile("cp.async.wait_group 0;" ::: "memory"); }
        __syncthreads();

        const u32 Ps = smb + (u32)(i % 3) * PV_STAGE;
        const u32 Vs = Ps + PV_PSTG;

#pragma unroll 2
        for (int k0 = 0; k0 < 128; k0 += 16) {
            u32 a0[4], a1[4];
            ldsm4(a0, Ps + aoff0 + k0 * 2);
            ldsm4(a1, Ps + aoff1 + k0 * 2);
#pragma unroll
            for (int fp = 0; fp < 4; fp++) {
                u32 bb[4];
                ldsm4(bb, Vs + boff + fp * (16 * 272) + k0 * 2);
                mma_bf16(pv[0][2 * fp],     a0, bb);
                mma_bf16(pv[0][2 * fp + 1], a0, bb + 2);
                mma_bf16(pv[1][2 * fp],     a1, bb);
                mma_bf16(pv[1][2 * fp + 1], a1, bb + 2);
            }
        }

        if ((i & 7) == 7) {
            int t = i >> 3;
#pragma unroll
            for (int mi = 0; mi < 2; mi++) {
                int r0 = qg * 32 + mi * 16 + gr;
                float inv0 = 1.0f / (3.0f * laccS[t * 128 + r0]);
                float inv1 = 1.0f / (3.0f * laccS[t * 128 + r0 + 8]);
#pragma unroll
                for (int f = 0; f < 8; f++) {
                    oacc[mi][f][0] += pv[mi][f][0] * inv0;
                    oacc[mi][f][1] += pv[mi][f][1] * inv0;
                    oacc[mi][f][2] += pv[mi][f][2] * inv1;
                    oacc[mi][f][3] += pv[mi][f][3] * inv1;
                }
            }
        }
        __syncthreads();       // stage (i%3) consumed by all warps

        if (i <= 20) issue(i + 3);
    }

    // epilogue: transpose via smem, out = student + fused (coalesced)
    float* stg = (float*)smc;   // [128 c][132 q] f32, overlays stage buffers
#pragma unroll
    for (int mi = 0; mi < 2; mi++) {
        int r0 = qg * 32 + mi * 16 + gr;
#pragma unroll
        for (int f = 0; f < 8; f++) {
            int c = cg * 64 + f * 8 + 2 * j;
            stg[c * 132 + r0]           = oacc[mi][f][0];
            stg[(c + 1) * 132 + r0]     = oacc[mi][f][1];
            stg[c * 132 + r0 + 8]       = oacc[mi][f][2];
            stg[(c + 1) * 132 + r0 + 8] = oacc[mi][f][3];
        }
    }
    __syncthreads();

    const float* stu  = student + ((size_t)b * NC + c0) * NN;
    float*       outp = out + ((size_t)b * NC + c0) * NN;
#pragma unroll
    for (int it = 0; it < 16; it++) {
        int idx = tid + 256 * it;          // 4096 float4 = 128c x 32 q4
        int c = idx >> 5, q4 = (idx & 31) * 4;
        size_t off = (size_t)c * NN + q0 + q4;
        float4 s4 = *(const float4*)&stg[c * 132 + q4];
        float4 bs = *(const float4*)&stu[off];
        float4 r;
        r.x = bs.x + s4.x; r.y = bs.y + s4.y;
        r.z = bs.z + s4.z; r.w = bs.w + s4.w;
        *(float4*)&outp[off] = r;
    }
}

// ---------------------------------------------------------------------------
extern "C" void kernel_launch(void* const* d_in, const int* in_sizes, int n_in,
                              void* d_out, int out_size)
{
    const float* student = (const float*)d_in[0];
    const float* t0 = (const float*)d_in[1];
    const float* t1 = (const float*)d_in[2];
    const float* t2 = (const float*)d_in[3];
    const float* Wq = (const float*)d_in[4];
    const float* bq = (const float*)d_in[5];
    const float* Wk = (const float*)d_in[6];
    const float* bk = (const float*)d_in[7];
    const float* Wv = (const float*)d_in[8];
    const float* bv = (const float*)d_in[9];
    float* out = (float*)d_out;

    zero_lacc_kernel<<<NT * NB, 1024>>>();

    dim3 pg(NN / 256, NC / 64, 7 * NB);
    proj_kernel<<<pg, 256>>>(Wq, bq, Wk, bk, Wv, bv, student, t0, t1, t2);

    cudaFuncSetAttribute(s_kernel, cudaFuncAttributeMaxDynamicSharedMemorySize,
                         S2_SMEM);
    s_kernel<<<dim3(NN / 256, NN / 128, NT * NB), 512, S2_SMEM>>>();

    cudaFuncSetAttribute(pv_kernel, cudaFuncAttributeMaxDynamicSharedMemorySize,
                         PV_BYTES);
    pv_kernel<<<dim3(NC / 128, NN / 128, NB), 256, PV_BYTES>>>(student, out);
}

// round 17
// speedup vs baseline: 1.2136x; 1.0093x over previous
#include <cuda_runtime.h>
#include <cuda_bf16.h>
#include <cstdint>

typedef uint32_t u32;
typedef uint16_t u16;

#define NB 8
#define NC 256
#define NN 1024
#define NT 3

// bf16 scratch: Q^T/K^T [.., n, c], V [.., c, n]
__device__ __align__(16) u16 g_QpT[NB * NN * NC];
__device__ __align__(16) u16 g_KpT[NT * NB * NN * NC];
__device__ __align__(16) u16 g_Vp [NT * NB * NC * NN];
// P = exp(S/16) bf16 [t*8+b][q][k]; lacc partials: [slot(2)][tb][q]
__device__ __align__(16) u16   g_P[(size_t)NT * NB * NN * NN];
__device__ float g_lacc2[2 * NT * NB * NN];

// ---------------- helpers ----------------
__device__ __forceinline__ u32 smem_u32(const void* p) {
    u32 a;
    asm("{ .reg .u64 t; cvta.to.shared.u64 t, %1; cvt.u32.u64 %0, t; }"
        : "=r"(a) : "l"(p));
    return a;
}
__device__ __forceinline__ void cp16(u32 dst, const void* src) {
    asm volatile("cp.async.cg.shared.global [%0], [%1], 16;"
                 :: "r"(dst), "l"(src) : "memory");
}
__device__ __forceinline__ void cp_commit() {
    asm volatile("cp.async.commit_group;" ::: "memory");
}
__device__ __forceinline__ void ldsm4(u32* r, u32 addr) {
    asm volatile("ldmatrix.sync.aligned.m8n8.x4.shared.b16 {%0,%1,%2,%3}, [%4];"
        : "=r"(r[0]), "=r"(r[1]), "=r"(r[2]), "=r"(r[3]) : "r"(addr));
}

__device__ __forceinline__ u32 pack_bf16(float lo, float hi) {
    u32 r; asm("cvt.rn.bf16x2.f32 %0, %1, %2;" : "=r"(r) : "f"(hi), "f"(lo)); return r;
}
__device__ __forceinline__ u16 bf16_bits(float f) {
    u16 r; asm("cvt.rn.bf16.f32 %0, %1;" : "=h"(r) : "f"(f)); return r;
}

__device__ __forceinline__ void mma_bf16(float* d, const u32* a, const u32* b) {
    asm volatile(
        "mma.sync.aligned.m16n8k16.row.col.f32.bf16.bf16.f32 "
        "{%0,%1,%2,%3}, {%4,%5,%6,%7}, {%8,%9}, {%0,%1,%2,%3};"
        : "+f"(d[0]), "+f"(d[1]), "+f"(d[2]), "+f"(d[3])
        : "r"(a[0]), "r"(a[1]), "r"(a[2]), "r"(a[3]), "r"(b[0]), "r"(b[1]));
}

__device__ __forceinline__ float fast_exp(float x) {
    float t = fmaf(x, 1.4426950408889634f, 12582912.0f);
    float n = t - 12582912.0f;
    int   e = __float_as_int(t) << 23;
    float r = fmaf(x, 1.4426950408889634f, -n);
    float p = 1.3333558146e-3f;
    p = fmaf(p, r, 9.6181291076e-3f);
    p = fmaf(p, r, 5.5504108665e-2f);
    p = fmaf(p, r, 2.4022650696e-1f);
    p = fmaf(p, r, 6.9314718056e-1f);
    p = fmaf(p, r, 1.0f);
    return __int_as_float(__float_as_int(p) + e);
}

// ---------------------------------------------------------------------------
// Projection via bf16 mma (m16n8k16), unchanged from R16 (proven).
// ---------------------------------------------------------------------------
#define PW_STR 40
#define PX_STR 264
#define PW_BYTES (64 * PW_STR * 2)
#define PSM_BYTES (256 * 72 * 2)

__global__ __launch_bounds__(256) void proj_kernel(
    const float* __restrict__ Wq, const float* __restrict__ bq,
    const float* __restrict__ Wk, const float* __restrict__ bk,
    const float* __restrict__ Wv, const float* __restrict__ bv,
    const float* __restrict__ xs, const float* __restrict__ x0,
    const float* __restrict__ x1, const float* __restrict__ x2)
{
    __shared__ __align__(16) char psm[PSM_BYTES];
    u16* Wsb = (u16*)psm;
    u32* Xp  = (u32*)(psm + PW_BYTES);
    u16* stg = (u16*)psm;

    const int tid  = threadIdx.x;
    const int wid  = tid >> 5, lane = tid & 31;
    const int gr   = lane >> 2, j = lane & 3;
    const int ow   = wid & 1, nw = wid >> 1;
    const int n0   = blockIdx.x * 256;
    const int o0   = blockIdx.y * 64;
    const int z    = blockIdx.z;
    const int p    = z >> 3, b = z & 7;

    const float* W; const float* bias; const float* X;
    u16* dst; bool vmode;
    if (p == 0) {
        W = Wq; bias = bq; X = xs + (size_t)b * NC * NN;
        dst = g_QpT + (size_t)b * NN * NC; vmode = false;
    } else if (p <= 3) {
        W = Wk; bias = bk;
        const float* tf = (p == 1) ? x0 : ((p == 2) ? x1 : x2);
        X = tf + (size_t)b * NC * NN;
        dst = g_KpT + ((size_t)(p - 1) * NB + b) * NN * NC; vmode = false;
    } else {
        W = Wv; bias = bv;
        const float* tf = (p == 4) ? x0 : ((p == 5) ? x1 : x2);
        X = tf + (size_t)b * NC * NN;
        dst = g_Vp + ((size_t)(p - 4) * NB + b) * NC * NN; vmode = true;
    }

    float d[2][8][4];
#pragma unroll
    for (int mi = 0; mi < 2; mi++)
#pragma unroll
        for (int f = 0; f < 8; f++)
#pragma unroll
            for (int e = 0; e < 4; e++) d[mi][f][e] = 0.0f;

    for (int c0 = 0; c0 < NC; c0 += 32) {
        __syncthreads();
#pragma unroll
        for (int it = 0; it < 2; it++) {
            int idx = tid + 256 * it;
            int r = idx >> 3, c4 = (idx & 7) * 4;
            float4 w4 = *(const float4*)&W[(size_t)(o0 + r) * NC + c0 + c4];
            uint2 pk;
            pk.x = pack_bf16(w4.x, w4.y);
            pk.y = pack_bf16(w4.z, w4.w);
            *(uint2*)&Wsb[r * PW_STR + c4] = pk;
        }
#pragma unroll
        for (int it = 0; it < 4; it++) {
            int idx = tid + 256 * it;
            int rp = idx >> 6, n4 = (idx & 63) * 4;
            const float* xr0 = &X[(size_t)(c0 + 2 * rp) * NN + n0 + n4];
            float4 xa = *(const float4*)xr0;
            float4 xb = *(const float4*)(xr0 + NN);
            uint4 pk;
            pk.x = pack_bf16(xa.x, xb.x);
            pk.y = pack_bf16(xa.y, xb.y);
            pk.z = pack_bf16(xa.z, xb.z);
            pk.w = pack_bf16(xa.w, xb.w);
            *(uint4*)&Xp[rp * PX_STR + n4] = pk;
        }
        __syncthreads();

#pragma unroll
        for (int kx = 0; kx < 2; kx++) {
            u32 a[2][4];
#pragma unroll
            for (int mi = 0; mi < 2; mi++) {
                int row = ow * 32 + mi * 16 + gr;
                const u16* base = &Wsb[row * PW_STR + kx * 16 + 2 * j];
                a[mi][0] = *(const u32*)(base);
                a[mi][1] = *(const u32*)(base + 8 * PW_STR);
                a[mi][2] = *(const u32*)(base + 8);
                a[mi][3] = *(const u32*)(base + 8 * PW_STR + 8);
            }
#pragma unroll
            for (int f = 0; f < 8; f++) {
                int n = nw * 64 + f * 8 + gr;
                u32 bb[2];
                bb[0] = Xp[(kx * 8 + j) * PX_STR + n];
                bb[1] = Xp[(kx * 8 + 4 + j) * PX_STR + n];
                mma_bf16(d[0][f], a[0], bb);
                mma_bf16(d[1][f], a[1], bb);
            }
        }
    }

    float bi[2][2];
#pragma unroll
    for (int mi = 0; mi < 2; mi++) {
        bi[mi][0] = bias[o0 + ow * 32 + mi * 16 + gr];
        bi[mi][1] = bias[o0 + ow * 32 + mi * 16 + gr + 8];
    }

    if (vmode) {
#pragma unroll
        for (int mi = 0; mi < 2; mi++) {
            int row0 = o0 + ow * 32 + mi * 16 + gr;
#pragma unroll
            for (int f = 0; f < 8; f++) {
                int n = n0 + nw * 64 + f * 8 + 2 * j;
                *(u32*)&dst[(size_t)row0 * NN + n] =
                    pack_bf16(d[mi][f][0] + bi[mi][0], d[mi][f][1] + bi[mi][0]);
                *(u32*)&dst[(size_t)(row0 + 8) * NN + n] =
                    pack_bf16(d[mi][f][2] + bi[mi][1], d[mi][f][3] + bi[mi][1]);
            }
        }
    } else {
        __syncthreads();
#pragma unroll
        for (int mi = 0; mi < 2; mi++) {
            int row0 = ow * 32 + mi * 16 + gr;
#pragma unroll
            for (int f = 0; f < 8; f++) {
                int n = nw * 64 + f * 8 + 2 * j;
                stg[n * 72 + row0]           = bf16_bits(d[mi][f][0] + bi[mi][0]);
                stg[(n + 1) * 72 + row0]     = bf16_bits(d[mi][f][1] + bi[mi][0]);
                stg[n * 72 + row0 + 8]       = bf16_bits(d[mi][f][2] + bi[mi][1]);
                stg[(n + 1) * 72 + row0 + 8] = bf16_bits(d[mi][f][3] + bi[mi][1]);
            }
        }
        __syncthreads();
#pragma unroll
        for (int it = 0; it < 8; it++) {
            int idx = tid + 256 * it;
            int n = idx >> 3, u = (idx & 7) * 8;
            *(uint4*)&dst[(size_t)(n0 + n) * NC + o0 + u] = *(const uint4*)&stg[n * 72 + u];
        }
    }
}

// ---------------------------------------------------------------------------
// S-kernel v3: CTA = 128 q x 512 keys (2 ktiles of 256), Q resident.
// Pipeline: Q group, then K(kt,half) stages double-buffered; K(s+2) issued
// BEFORE the kt epilogue so exp/P-store overlaps the next load.
// Row sums: smem cross-warp reduce -> register -> g_lacc2 (no atomics).
// Grid (2, 8, 24), 512 threads.
// ---------------------------------------------------------------------------
#define S3_Q     0                         // 2 halves x 34816 = 69632
#define S3_KBUF  69632                     // 2 bufs x 69632 = 139264
#define S3_SL    208896                    // [128 rows][4 kg] floats = 2048 B
#define S3_SMEM  210944

__global__ __launch_bounds__(512, 1) void s_kernel()
{
    extern __shared__ __align__(16) char smc[];
    float* sl = (float*)(smc + S3_SL);
    const u32 smb = smem_u32(smc);

    const int tid  = threadIdx.x;
    const int wid  = tid >> 5, lane = tid & 31;
    const int gr   = lane >> 2, j = lane & 3;
    const int qg   = wid & 3, kg = wid >> 2;
    const int kbb  = blockIdx.x * 512;
    const int q0   = blockIdx.y * 128;
    const int tb   = blockIdx.z;
    const int b    = tb & 7;

    const u16* Qg = g_QpT + ((size_t)b * NN + q0) * NC;
    const u16* Kg = g_KpT + ((size_t)tb * NN + kbb) * NC;

    const int lrow = (lane & 7) + ((lane >> 3) & 1) * 8;
    const u32 aoff0 = (u32)(qg * 32 + lrow) * 272 + ((lane >> 4) & 1) * 16;
    const u32 aoff1 = aoff0 + 16 * 272;
    const u32 boff  = (u32)(kg * 64 + (lane & 7) + ((lane >> 4) & 1) * 8) * 272
                      + ((lane >> 3) & 1) * 16;

    // Q group: both c-halves (4096 cp16)
#pragma unroll
    for (int it = 0; it < 8; it++) {
        int idx = tid + 512 * it;
        int h = idx >> 11, rem = idx & 2047;
        int r = rem >> 4, u = (rem & 15) * 8;
        cp16(smb + S3_Q + h * 34816 + r * 272 + u * 2,
             &Qg[(size_t)r * NC + h * 128 + u]);
    }
    cp_commit();

    auto issueK = [&](int s) {             // s = kt*2 + half
        int kt = s >> 1, h = s & 1;
        u32 base = smb + S3_KBUF + (u32)(s & 1) * 69632;
        const u16* src = Kg + (size_t)(kt * 256) * NC + h * 128;
#pragma unroll
        for (int it = 0; it < 8; it++) {
            int idx = tid + 512 * it;
            int r = idx >> 4, u = (idx & 15) * 8;
            cp16(base + r * 272 + u * 2, &src[(size_t)r * NC + u]);
        }
        cp_commit();
    };

    issueK(0);
    issueK(1);

    u16* Pg = g_P + (size_t)tb * NN * NN;
    float ctaSum = 0.0f;                   // valid for tid < 128 (row = tid)
    float sacc[2][8][4];

    for (int s = 0; s < 4; s++) {
        const int kt = s >> 1, h = s & 1;
        if (s < 3) { asm volatile("cp.async.wait_group 1;" ::: "memory"); }
        else       { asm volatile("cp.async.wait_group 0;" ::: "memory"); }
        __syncthreads();

        if (h == 0) {
#pragma unroll
            for (int mi = 0; mi < 2; mi++)
#pragma unroll
                for (int f = 0; f < 8; f++)
#pragma unroll
                    for (int e = 0; e < 4; e++) sacc[mi][f][e] = 0.0f;
        }

        const u32 Qs = smb + S3_Q + (u32)h * 34816;
        const u32 Ks = smb + S3_KBUF + (u32)(s & 1) * 69632;

#pragma unroll 4
        for (int cc = 0; cc < 128; cc += 16) {
            u32 a0[4], a1[4];
            ldsm4(a0, Qs + aoff0 + cc * 2);
            ldsm4(a1, Qs + aoff1 + cc * 2);
#pragma unroll
            for (int fp = 0; fp < 4; fp++) {
                u32 bb[4];
                ldsm4(bb, Ks + boff + fp * (16 * 272) + cc * 2);
                mma_bf16(sacc[0][2 * fp],     a0, bb);
                mma_bf16(sacc[0][2 * fp + 1], a0, bb + 2);
                mma_bf16(sacc[1][2 * fp],     a1, bb);
                mma_bf16(sacc[1][2 * fp + 1], a1, bb + 2);
            }
        }
        __syncthreads();                   // buffer consumed by all warps

        if (s + 2 < 4) issueK(s + 2);      // overlaps epilogue below

        if (h == 1) {
            // epilogue for this kt: exp, P store, cross-warp row sums
            const int kbase = kbb + kt * 256;
#pragma unroll
            for (int mi = 0; mi < 2; mi++) {
                int r0 = qg * 32 + mi * 16 + gr;
                float rs0 = 0.0f, rs1 = 0.0f;
#pragma unroll
                for (int f = 0; f < 8; f++) {
                    float p0 = fast_exp(sacc[mi][f][0] * 0.0625f);
                    float p1 = fast_exp(sacc[mi][f][1] * 0.0625f);
                    float p2 = fast_exp(sacc[mi][f][2] * 0.0625f);
                    float p3 = fast_exp(sacc[mi][f][3] * 0.0625f);
                    rs0 += p0 + p1; rs1 += p2 + p3;
                    int col = kbase + kg * 64 + f * 8 + 2 * j;
                    *(u32*)&Pg[(size_t)(q0 + r0) * NN + col]     = pack_bf16(p0, p1);
                    *(u32*)&Pg[(size_t)(q0 + r0 + 8) * NN + col] = pack_bf16(p2, p3);
                }
                rs0 += __shfl_xor_sync(0xffffffffu, rs0, 1);
                rs0 += __shfl_xor_sync(0xffffffffu, rs0, 2);
                rs1 += __shfl_xor_sync(0xffffffffu, rs1, 1);
                rs1 += __shfl_xor_sync(0xffffffffu, rs1, 2);
                if (j == 0) {
                    sl[r0 * 4 + kg]       = rs0;
                    sl[(r0 + 8) * 4 + kg] = rs1;
                }
            }
            __syncthreads();
            if (tid < 128)
                ctaSum += sl[tid * 4] + sl[tid * 4 + 1]
                        + sl[tid * 4 + 2] + sl[tid * 4 + 3];
        }
    }

    if (tid < 128)
        g_lacc2[((size_t)blockIdx.x * (NT * NB) + tb) * NN + q0 + tid] = ctaSum;
}

// ---------------------------------------------------------------------------
// PV-kernel: unchanged structure (proven, at mma ceiling); lacc = sum of 2 slots.
// ---------------------------------------------------------------------------
#define PV_PSTG  34816
#define PV_STAGE 69632
#define PV_LACC  208896
#define PV_BYTES (PV_LACC + 3 * 128 * 4)

__global__ __launch_bounds__(256, 1) void pv_kernel(
    const float* __restrict__ student, float* __restrict__ out)
{
    extern __shared__ __align__(16) char smc[];
    float* laccS = (float*)(smc + PV_LACC);
    const u32 smb = smem_u32(smc);

    const int tid  = threadIdx.x;
    const int wid  = tid >> 5, lane = tid & 31;
    const int gr   = lane >> 2, j = lane & 3;
    const int qg   = wid & 3, cg = wid >> 2;
    const int c0   = blockIdx.x * 128;
    const int q0   = blockIdx.y * 128;
    const int b    = blockIdx.z;

    const int lrow = (lane & 7) + ((lane >> 3) & 1) * 8;
    const u32 aoff0 = (u32)(qg * 32 + lrow) * 272 + ((lane >> 4) & 1) * 16;
    const u32 aoff1 = aoff0 + 16 * 272;
    const u32 boff  = (u32)(cg * 64 + (lane & 7) + ((lane >> 4) & 1) * 8) * 272
                      + ((lane >> 3) & 1) * 16;

    for (int i = tid; i < 384; i += 256) {
        int t = i >> 7, q = i & 127;
        laccS[i] = g_lacc2[((size_t)(t * 8 + b)) * NN + q0 + q]
                 + g_lacc2[((size_t)(NT * NB + t * 8 + b)) * NN + q0 + q];
    }

    auto issue = [&](int i) {
        int t = i >> 3, kc = i & 7;
        const u16* Pg = g_P  + ((size_t)(t * 8 + b) * NN + q0) * NN + kc * 128;
        const u16* Vg = g_Vp + ((size_t)(t * 8 + b) * NC + c0) * NN + kc * 128;
        u32 base = smb + (u32)(i % 3) * PV_STAGE;
#pragma unroll
        for (int it = 0; it < 8; it++) {
            int idx = tid + 256 * it;
            int r = idx >> 4, u = (idx & 15) * 8;
            cp16(base + r * 272 + u * 2, &Pg[(size_t)r * NN + u]);
        }
#pragma unroll
        for (int it = 0; it < 8; it++) {
            int idx = tid + 256 * it;
            int r = idx >> 4, u = (idx & 15) * 8;
            cp16(base + PV_PSTG + r * 272 + u * 2, &Vg[(size_t)r * NN + u]);
        }
        cp_commit();
    };

    float oacc[2][8][4], pv[2][8][4];
#pragma unroll
    for (int mi = 0; mi < 2; mi++)
#pragma unroll
        for (int f = 0; f < 8; f++)
#pragma unroll
            for (int e = 0; e < 4; e++) oacc[mi][f][e] = 0.0f;

    issue(0); issue(1); issue(2);

    for (int i = 0; i < 24; i++) {
        if ((i & 7) == 0) {
#pragma unroll
            for (int mi = 0; mi < 2; mi++)
#pragma unroll
                for (int f = 0; f < 8; f++)
#pragma unroll
                    for (int e = 0; e < 4; e++) pv[mi][f][e] = 0.0f;
        }

        if (i < 22)      { asm volatile("cp.async.wait_group 2;" ::: "memory"); }
        else if (i == 22){ asm volatile("cp.async.wait_group 1;" ::: "memory"); }
        else             { asm volatile("cp.async.wait_group 0;" ::: "memory"); }
        __syncthreads();

        const u32 Ps = smb + (u32)(i % 3) * PV_STAGE;
        const u32 Vs = Ps + PV_PSTG;

#pragma unroll 2
        for (int k0 = 0; k0 < 128; k0 += 16) {
            u32 a0[4], a1[4];
            ldsm4(a0, Ps + aoff0 + k0 * 2);
            ldsm4(a1, Ps + aoff1 + k0 * 2);
#pragma unroll
            for (int fp = 0; fp < 4; fp++) {
                u32 bb[4];
                ldsm4(bb, Vs + boff + fp * (16 * 272) + k0 * 2);
                mma_bf16(pv[0][2 * fp],     a0, bb);
                mma_bf16(pv[0][2 * fp + 1], a0, bb + 2);
                mma_bf16(pv[1][2 * fp],     a1, bb);
                mma_bf16(pv[1][2 * fp + 1], a1, bb + 2);
            }
        }

        if ((i & 7) == 7) {
            int t = i >> 3;
#pragma unroll
            for (int mi = 0; mi < 2; mi++) {
                int r0 = qg * 32 + mi * 16 + gr;
                float inv0 = 1.0f / (3.0f * laccS[t * 128 + r0]);
                float inv1 = 1.0f / (3.0f * laccS[t * 128 + r0 + 8]);
#pragma unroll
                for (int f = 0; f < 8; f++) {
                    oacc[mi][f][0] += pv[mi][f][0] * inv0;
                    oacc[mi][f][1] += pv[mi][f][1] * inv0;
                    oacc[mi][f][2] += pv[mi][f][2] * inv1;
                    oacc[mi][f][3] += pv[mi][f][3] * inv1;
                }
            }
        }
        __syncthreads();

        if (i <= 20) issue(i + 3);
    }

    float* stg = (float*)smc;
#pragma unroll
    for (int mi = 0; mi < 2; mi++) {
        int r0 = qg * 32 + mi * 16 + gr;
#pragma unroll
        for (int f = 0; f < 8; f++) {
            int c = cg * 64 + f * 8 + 2 * j;
            stg[c * 132 + r0]           = oacc[mi][f][0];
            stg[(c + 1) * 132 + r0]     = oacc[mi][f][1];
            stg[c * 132 + r0 + 8]       = oacc[mi][f][2];
            stg[(c + 1) * 132 + r0 + 8] = oacc[mi][f][3];
        }
    }
    __syncthreads();

    const float* stu  = student + ((size_t)b * NC + c0) * NN;
    float*       outp = out + ((size_t)b * NC + c0) * NN;
#pragma unroll
    for (int it = 0; it < 16; it++) {
        int idx = tid + 256 * it;
        int c = idx >> 5, q4 = (idx & 31) * 4;
        size_t off = (size_t)c * NN + q0 + q4;
        float4 s4 = *(const float4*)&stg[c * 132 + q4];
        float4 bs = *(const float4*)&stu[off];
        float4 r;
        r.x = bs.x + s4.x; r.y = bs.y + s4.y;
        r.z = bs.z + s4.z; r.w = bs.w + s4.w;
        *(float4*)&outp[off] = r;
    }
}

// ---------------------------------------------------------------------------
extern "C" void kernel_launch(void* const* d_in, const int* in_sizes, int n_in,
                              void* d_out, int out_size)
{
    const float* student = (const float*)d_in[0];
    const float* t0 = (const float*)d_in[1];
    const float* t1 = (const float*)d_in[2];
    const float* t2 = (const float*)d_in[3];
    const float* Wq = (const float*)d_in[4];
    const float* bq = (const float*)d_in[5];
    const float* Wk = (const float*)d_in[6];
    const float* bk = (const float*)d_in[7];
    const float* Wv = (const float*)d_in[8];
    const float* bv = (const float*)d_in[9];
    float* out = (float*)d_out;

    dim3 pg(NN / 256, NC / 64, 7 * NB);
    proj_kernel<<<pg, 256>>>(Wq, bq, Wk, bk, Wv, bv, student, t0, t1, t2);

    cudaFuncSetAttribute(s_kernel, cudaFuncAttributeMaxDynamicSharedMemorySize,
                         S3_SMEM);
    s_kernel<<<dim3(NN / 512, NN / 128, NT * NB), 512, S3_SMEM>>>();

    cudaFuncSetAttribute(pv_kernel, cudaFuncAttributeMaxDynamicSharedMemorySize,
                         PV_BYTES);
    pv_kernel<<<dim3(NC / 128, NN / 128, NB), 256, PV_BYTES>>>(student, out);
}